// round 2
// baseline (speedup 1.0000x reference)
#include <cuda_runtime.h>
#include <math.h>

// FFM forward: out[b] = sigmoid( relu(feats@Wd + bd) + sum_{i<j} <v_i[j-1], v_j[i]> )
// v_i[slot] = mean over seq of E_i[slot][x_i[b,s]]   (E_i shape: (5, DIM_i, 16))
// feats[i]  = mean over seq of L_i[x_i[b,s]]

#define WARPS_PER_BLOCK 8
#define BATCH 16384

__constant__ int c_pair_i[15] = {0,0,0,0,0,1,1,1,1,2,2,2,3,3,4};
__constant__ int c_pair_j[15] = {1,2,3,4,5,2,3,4,5,3,4,5,4,5,5};

template<int SEQN>
__device__ __forceinline__ void process_field(
    const int* __restrict__ x, const float* __restrict__ E,
    const float* __restrict__ L, int dim, int b, int lane,
    float* __restrict__ v_field,   // [5][16] floats, 16B aligned
    float* __restrict__ feat)
{
    const int slot  = lane >> 2;   // 0..7 (active <5)
    const int chunk = lane & 3;    // float4 chunk within 16-dim row
    float4 acc = make_float4(0.f, 0.f, 0.f, 0.f);
    float  lacc = 0.f;
    const int* xb = x + (size_t)b * SEQN;

#pragma unroll
    for (int s = 0; s < SEQN; ++s) {
        const int idx = __ldg(xb + s);
        if (lane < 20) {
            const float4* p =
                reinterpret_cast<const float4*>(E + ((size_t)slot * dim + idx) * 16) + chunk;
            float4 e = __ldg(p);
            acc.x += e.x; acc.y += e.y; acc.z += e.z; acc.w += e.w;
        } else if (lane == 20) {
            lacc += __ldg(L + idx);
        }
    }
    const float inv = 1.0f / (float)SEQN;
    if (lane < 20) {
        float4 r = make_float4(acc.x * inv, acc.y * inv, acc.z * inv, acc.w * inv);
        *reinterpret_cast<float4*>(v_field + slot * 16 + chunk * 4) = r;
    } else if (lane == 20) {
        *feat = lacc * inv;
    }
}

extern "C" __global__ void __launch_bounds__(WARPS_PER_BLOCK * 32)
ffm_kernel(const int* __restrict__ x0, const int* __restrict__ x1,
           const int* __restrict__ x2, const int* __restrict__ x3,
           const int* __restrict__ x4, const int* __restrict__ x5,
           const float* __restrict__ E0, const float* __restrict__ E1,
           const float* __restrict__ E2, const float* __restrict__ E3,
           const float* __restrict__ E4, const float* __restrict__ E5,
           const float* __restrict__ L0, const float* __restrict__ L1,
           const float* __restrict__ L2, const float* __restrict__ L3,
           const float* __restrict__ L4, const float* __restrict__ L5,
           const float* __restrict__ Wd, const float* __restrict__ bd,
           float* __restrict__ out)
{
    __shared__ __align__(16) float sv[WARPS_PER_BLOCK][6 * 80]; // 6 fields x 5 slots x 16
    __shared__ float sfeat[WARPS_PER_BLOCK][6];

    const int warp = threadIdx.x >> 5;
    const int lane = threadIdx.x & 31;
    const int b = blockIdx.x * WARPS_PER_BLOCK + warp;
    if (b >= BATCH) return;

    float* v    = sv[warp];
    float* feat = sfeat[warp];

    process_field<1 >(x0, E0, L0, 1000000, b, lane, v + 0 * 80, feat + 0);
    process_field<1 >(x1, E1, L1,  500000, b, lane, v + 1 * 80, feat + 1);
    process_field<50>(x2, E2, L2,  500000, b, lane, v + 2 * 80, feat + 2);
    process_field<20>(x3, E3, L3,  100000, b, lane, v + 3 * 80, feat + 3);
    process_field<1 >(x4, E4, L4,   10000, b, lane, v + 4 * 80, feat + 4);
    process_field<1 >(x5, E5, L5,    1000, b, lane, v + 5 * 80, feat + 5);

    __syncwarp();

    // fm = sum over 15 pairs (i<j) of dot16(v_i[j-1], v_j[i])
    // 15 pairs x 4 float4-chunks = 60 work items over 32 lanes (2 rounds)
    float partial = 0.f;
#pragma unroll
    for (int r = 0; r < 2; ++r) {
        const int item = lane + r * 32;
        if (item < 60) {
            const int t = item >> 2;
            const int c = item & 3;
            const int i = c_pair_i[t];
            const int j = c_pair_j[t];
            const float4 a  = *reinterpret_cast<const float4*>(v + i * 80 + (j - 1) * 16 + c * 4);
            const float4 bb = *reinterpret_cast<const float4*>(v + j * 80 +  i      * 16 + c * 4);
            partial += a.x * bb.x + a.y * bb.y + a.z * bb.z + a.w * bb.w;
        }
    }
#pragma unroll
    for (int off = 16; off; off >>= 1)
        partial += __shfl_xor_sync(0xffffffffu, partial, off);

    if (lane == 0) {
        float lin = __ldg(bd);
#pragma unroll
        for (int i = 0; i < 6; ++i) lin += feat[i] * __ldg(Wd + i);
        lin = fmaxf(lin, 0.f);
        const float z = lin + partial;
        out[b] = 1.0f / (1.0f + expf(-z));
    }
}

extern "C" void kernel_launch(void* const* d_in, const int* in_sizes, int n_in,
                              void* d_out, int out_size)
{
    // First 6 inputs are x0..x5 in order (both candidate orderings agree).
    const int* xs[6];
    for (int i = 0; i < 6; ++i) xs[i] = (const int*)d_in[i];

    // The next 12 inputs are E0..E5 and L0..L5 in UNKNOWN interleaving
    // (dict order is E0,L0,E1,L1,... ; signature order is E0..E5,L0..L5).
    // Disambiguate by element count: E_i has 80*DIM_i elements, L_i has DIM_i.
    // E sizes {80M,40M,40M,8M,800K,80K} and L sizes {1M,500K,500K,100K,10K,1K}
    // are disjoint sets; within each set the encounter order equals field order.
    const float* E[6] = {0,0,0,0,0,0};
    const float* L[6] = {0,0,0,0,0,0};
    const float* Wd = 0;
    const float* bd = 0;
    int ei = 0, li = 0;
    for (int k = 6; k < n_in; ++k) {
        const long long sz = (long long)in_sizes[k];
        const float* p = (const float*)d_in[k];
        if (sz == 80000000LL || sz == 40000000LL || sz == 8000000LL ||
            sz == 800000LL   || sz == 80000LL) {
            if (ei < 6) E[ei++] = p;
        } else if (sz == 1000000LL || sz == 500000LL || sz == 100000LL ||
                   sz == 10000LL   || sz == 1000LL) {
            if (li < 6) L[li++] = p;
        } else if (sz == 6LL) {
            Wd = p;
        } else if (sz == 1LL) {
            bd = p;
        }
    }

    float* out = (float*)d_out;

    const int blocks = BATCH / WARPS_PER_BLOCK; // 2048
    ffm_kernel<<<blocks, WARPS_PER_BLOCK * 32>>>(
        xs[0], xs[1], xs[2], xs[3], xs[4], xs[5],
        E[0], E[1], E[2], E[3], E[4], E[5],
        L[0], L[1], L[2], L[3], L[4], L[5],
        Wd, bd, out);
}